// round 17
// baseline (speedup 1.0000x reference)
#include <cuda_runtime.h>
#include <cstdint>

#define NN 4096
#define HH 256
#define SS 128
#define RPB1 32

// ---------------- persistent device scratch ----------------
__device__ __align__(16) float d_HW0[NN*HH];     // h0 @ Wn
__device__ __align__(16) float d_HGseq[SS*HH];   // h0[seq[t]] @ Wg_bot (per step)
__device__ __align__(16) float d_FS[SS*HH];      // inp_t @ Ws + bs
__device__ __align__(16) float d_GI[SS*HH];      // inp_t @ Wg_top + bg
__device__ __align__(16) float d_NW0p[8][SS*HH]; // partial (nei_t @ h0) @ Wn
__device__ __align__(16) float d_S2p[8][SS*HH];  // partial S2base
__device__ __align__(16) float d_hidver[SS*HH];  // curHidden of step t
__device__ __align__(16) float d_pairWT[SS*SS];  // pairWT[t*SS+u] = nei[seq[t]][seq[u]]
__device__ float d_invN[SS];
__device__ int   d_lastVisit[SS];
__device__ int   d_lastStep[NN];

__device__ __forceinline__ float sig_t(float x) {   // sigmoid via tanh.approx (1 MUFU)
    float t;
    asm("tanh.approx.f32 %0, %1;" : "=f"(t) : "f"(0.5f * x));
    return fmaf(0.5f, t, 0.5f);
}
__device__ __forceinline__ float tanh_a(float x) {  // tanh.approx (1 MUFU)
    float t;
    asm("tanh.approx.f32 %0, %1;" : "=f"(t) : "f"(x));
    return t;
}

__global__ void k_init() {
    int e = blockIdx.x * blockDim.x + threadIdx.x;
    if (e < NN) d_lastStep[e] = -1;
}

__global__ void __launch_bounds__(256) k_pre1(
    const float* __restrict__ inputs, const float* __restrict__ nei,
    const float* __restrict__ numNei, const int* __restrict__ seq,
    const float* __restrict__ h0,
    const float* __restrict__ Wg, const float* __restrict__ bg,
    const float* __restrict__ Ws, const float* __restrict__ bs,
    const float* __restrict__ Wn)
{
    const int tid = threadIdx.x, b = blockIdx.x;
    __shared__ float sh[RPB1 * 256];

    const int r0 = b * RPB1;
    for (int e = tid; e < RPB1*256; e += 256) sh[e] = h0[(size_t)r0*256 + e];
    __syncthreads();
    {
        // HW0 = h0 @ Wn only (HG needed just for seq rows; done below)
        const int hq = (tid & 63) * 4;     // 4 h-columns per thread
        const int rg = (tid >> 6) * 8;     // 8 rows per thread
        float acc[8][4];
        #pragma unroll
        for (int r = 0; r < 8; ++r)
            #pragma unroll
            for (int c = 0; c < 4; ++c) acc[r][c] = 0.f;
        for (int k = 0; k < 256; ++k) {
            float4 wv = *(const float4*)&Wn[k*256 + hq];
            #pragma unroll
            for (int r = 0; r < 8; ++r) {
                float a = sh[(rg + r)*256 + k];
                acc[r][0] = fmaf(a, wv.x, acc[r][0]);
                acc[r][1] = fmaf(a, wv.y, acc[r][1]);
                acc[r][2] = fmaf(a, wv.z, acc[r][2]);
                acc[r][3] = fmaf(a, wv.w, acc[r][3]);
            }
        }
        #pragma unroll
        for (int r = 0; r < 8; ++r)
            *(float4*)&d_HW0[(size_t)(r0 + rg + r)*256 + hq] =
                make_float4(acc[r][0], acc[r][1], acc[r][2], acc[r][3]);
    }
    __syncthreads();

    {   // b in [0, SS): FS/GI/HGseq for step b + pairWT column
        int ii = __ldg(&seq[b]);
        for (int k = tid; k < 256; k += 256) {
            sh[k]       = inputs[(size_t)ii*256 + k];   // input row
            sh[256 + k] = h0[(size_t)ii*256 + k];       // h0 row (for HGseq)
        }
        __syncthreads();
        const int h = tid;
        float fs = bs[h], gi = bg[h], hg = 0.f;
        for (int k = 0; k < 256; ++k) {
            float iv = sh[k];
            float hv = sh[256 + k];
            fs = fmaf(iv, __ldg(&Ws[k*256 + h]), fs);
            gi = fmaf(iv, __ldg(&Wg[k*256 + h]), gi);
            hg = fmaf(hv, __ldg(&Wg[(256 + k)*256 + h]), hg);
        }
        d_FS[b*256 + h]    = fs;
        d_GI[b*256 + h]    = gi;
        d_HGseq[b*256 + h] = hg;
        if (tid < SS) {
            int tseq = __ldg(&seq[tid]);
            d_pairWT[tid*SS + b] = __ldg(&nei[(size_t)tseq*NN + ii]);
        }
    }

    if (b == 0 && tid < SS) {
        int me = __ldg(&seq[tid]);
        int lv = -1;
        for (int u = tid - 1; u >= 0; --u)
            if (__ldg(&seq[u]) == me) { lv = u; break; }
        d_lastVisit[tid] = lv;
        atomicMax(&d_lastStep[me], tid);
        d_invN[tid] = 1.0f / __ldg(&numNei[me]);
    }
}

// S2base / NW0 partials: 8 t's x 512 j's per block; grid (16, 8) = 128 blocks
#define T_PER 8
__global__ void __launch_bounds__(256) k_pre2(const float* __restrict__ nei,
                                              const int* __restrict__ seq)
{
    const int tid = threadIdx.x;
    const int tt0 = blockIdx.x * T_PER, j0 = blockIdx.y * 512, by = blockIdx.y;
    __shared__ float shw[T_PER][512];
    int sqs[T_PER];
    #pragma unroll
    for (int q = 0; q < T_PER; ++q) sqs[q] = __ldg(&seq[tt0 + q]);
    for (int e = tid; e < T_PER*512; e += 256) {
        int q = e >> 9, j = e & 511;
        shw[q][j] = __ldg(&nei[(size_t)sqs[q]*NN + j0 + j]);
    }
    __syncthreads();
    const int h = tid;
    float fs[T_PER], s1[T_PER], s2[T_PER];
    #pragma unroll
    for (int q = 0; q < T_PER; ++q) {
        fs[q] = __ldg(&d_FS[(tt0+q)*256 + h]); s1[q] = 0.f; s2[q] = 0.f;
    }
    #pragma unroll 2
    for (int j = 0; j < 512; ++j) {
        float hw = __ldg(&d_HW0[(size_t)(j0+j)*256 + h]);
        #pragma unroll
        for (int q = 0; q < T_PER; ++q) {
            float w = shw[q][j];
            s1[q] = fmaf(w, hw, s1[q]);
            s2[q] = fmaf(w, sig_t(fs[q] + hw), s2[q]);
        }
    }
    #pragma unroll
    for (int q = 0; q < T_PER; ++q) {
        d_NW0p[by][(tt0+q)*256 + h] = s1[q];
        d_S2p [by][(tt0+q)*256 + h] = s2[q];
    }
}

// ---------------- main serial loop (templated on cluster size) ----------------
template<int NCTA> struct Cfg {
    static constexpr int W    = 256 / NCTA;      // warps per CTA (1 per owned h)
    static constexpr int NT   = W * 32;
    static constexpr int O_WN   = 0;             // [W][256]
    static constexpr int O_PW   = O_WN + W*256;  // [SS][SS]
    static constexpr int O_FS   = O_PW + SS*SS;  // [SS][W]
    static constexpr int O_GIPN = O_FS + SS*W;
    static constexpr int O_S2N  = O_GIPN + SS*W;
    static constexpr int O_C0   = O_S2N + SS*W;
    static constexpr int O_HW0G = O_C0 + SS*W;
    static constexpr int O_HG0G = O_HW0G + SS*W;
    static constexpr int O_CELL = O_HG0G + SS*W;
    static constexpr int O_INV  = O_CELL + SS*W; // [SS]
    static constexpr int O_HIDB = O_INV + SS;    // [2][256]
    static constexpr int O_END  = O_HIDB + 2*HH;
    static constexpr int FLAG_BYTE = ((O_END*4 + SS*4) + 15) & ~15;
    static constexpr int SMB = FLAG_BYTE + 128;
};

__device__ __forceinline__ uint32_t smem_u32(const void* p) {
    uint32_t a;
    asm("{ .reg .u64 t; cvta.to.shared.u64 t, %1; cvt.u32.u64 %0, t; }"
        : "=r"(a) : "l"(p));
    return a;
}
__device__ __forceinline__ uint32_t mapa_rank(uint32_t addr, int rank) {
    uint32_t r;
    asm("mapa.shared::cluster.u32 %0, %1, %2;" : "=r"(r) : "r"(addr), "r"(rank));
    return r;
}
__device__ __forceinline__ unsigned ld_acq_sh(uint32_t addr) {
    unsigned v;
    asm volatile("ld.acquire.cluster.shared::cta.b32 %0, [%1];"
                 : "=r"(v) : "r"(addr) : "memory");
    return v;
}
__device__ __forceinline__ void st_rlx_rem(uint32_t addr, float v) {
    asm volatile("st.relaxed.cluster.shared::cluster.b32 [%0], %1;"
                 :: "r"(addr), "r"(__float_as_uint(v)) : "memory");
}
__device__ __forceinline__ void st_rel_rem(uint32_t addr, unsigned v) {
    asm volatile("st.release.cluster.shared::cluster.b32 [%0], %1;"
                 :: "r"(addr), "r"(v) : "memory");
}

template<int NCTA>
__device__ __forceinline__ void k_main_body(
    const float* __restrict__ Wn, const float* __restrict__ Wg,
    const int* __restrict__ seq, const float* __restrict__ c0)
{
    using C = Cfg<NCTA>;
    constexpr int W = C::W;
    extern __shared__ __align__(16) float sm[];
    int* sslv = (int*)(sm + C::O_END);
    const uint32_t smbase = smem_u32(sm);
    const uint32_t flagbase = smbase + C::FLAG_BYTE;

    const int tid  = threadIdx.x;
    const int wid  = tid >> 5;
    const int lane = tid & 31;
    const int rank = blockIdx.x;
    const int h_base = rank * W;
    const int h = h_base + wid;

    // -------- preamble --------
    for (int k = lane; k < 256; k += 32)
        sm[C::O_WN + wid*256 + k] = __ldg(&Wn[k*256 + h]);
    for (int e = tid; e < SS*SS; e += C::NT)
        sm[C::O_PW + e] = d_pairWT[e];
    for (int e = tid; e < SS*W; e += C::NT) {
        int t = e / W, hl = e % W;
        int hcol = h_base + hl;
        int node = __ldg(&seq[t]);
        float invn = d_invN[t];
        float nv = 0.f, s2v = 0.f;
        #pragma unroll
        for (int p = 0; p < 8; ++p) {
            nv  += d_NW0p[p][t*256 + hcol];
            s2v += d_S2p [p][t*256 + hcol];
        }
        sm[C::O_FS   + e] = d_FS[t*256 + hcol];
        sm[C::O_GIPN + e] = d_GI[t*256 + hcol] + nv * invn;
        sm[C::O_S2N  + e] = s2v * invn;
        sm[C::O_C0   + e] = __ldg(&c0[(size_t)node*256 + hcol]);
        sm[C::O_HW0G + e] = d_HW0[(size_t)node*256 + hcol];
        sm[C::O_HG0G + e] = d_HGseq[t*256 + hcol];
    }
    if (tid < SS) {
        sslv[tid] = d_lastVisit[tid];
        sm[C::O_INV + tid] = d_invN[tid];
    }
    if (tid < NCTA) ((unsigned*)(sm + (C::FLAG_BYTE/4)))[tid] = 0u;
    __syncthreads();
    asm volatile("barrier.cluster.arrive.aligned;" ::: "memory");
    asm volatile("barrier.cluster.wait.aligned;" ::: "memory");

    // per-lane visit-slot caches: slot u = lane + 32*q
    float hv0=0.f,hv1=0.f,hv2=0.f,hv3=0.f;
    float hb0=0.f,hb1=0.f,hb2=0.f,hb3=0.f;

    for (int t = 0; t < SS; ++t) {
        const int lv = sslv[t];
        const float fsv = sm[C::O_FS + t*W + wid];
        const int pb = (t - 1) & 1;
        const float* pw = sm + C::O_PW + t*SS;

        // ===== pre-wait (overlaps previous step's communication) =====
        float s1p = 0.f, s2p = 0.f;
        const int lim = t - 2;
        if (lane <= lim) {
            float w = pw[lane];
            s1p = fmaf(w, hv0 - hb0, s1p);
            s2p = fmaf(w, sig_t(fsv + hv0) - sig_t(fsv + hb0), s2p);
        }
        if (lane + 32 <= lim) {
            float w = pw[lane + 32];
            s1p = fmaf(w, hv1 - hb1, s1p);
            s2p = fmaf(w, sig_t(fsv + hv1) - sig_t(fsv + hb1), s2p);
        }
        if (lane + 64 <= lim) {
            float w = pw[lane + 64];
            s1p = fmaf(w, hv2 - hb2, s1p);
            s2p = fmaf(w, sig_t(fsv + hv2) - sig_t(fsv + hb2), s2p);
        }
        if (lane + 96 <= lim) {
            float w = pw[lane + 96];
            s1p = fmaf(w, hv3 - hb3, s1p);
            s2p = fmaf(w, sig_t(fsv + hv3) - sig_t(fsv + hb3), s2p);
        }
        #pragma unroll
        for (int o = 16; o; o >>= 1) {          // full reduce pre-wait
            s1p += __shfl_xor_sync(0xffffffffu, s1p, o);
            s2p += __shfl_xor_sync(0xffffffffu, s2p, o);
        }

        // revisit prep (lv <= t-2)
        float hv_sel = 0.f, hgdyn = 0.f;
        const bool lv_old = (lv >= 0) && (lv < t - 1);
        if (lv_old) {
            int q = lv >> 5;
            float s = (q == 0) ? hv0 : (q == 1) ? hv1 : (q == 2) ? hv2 : hv3;
            hv_sel = __shfl_sync(0xffffffffu, s, lv & 31);
            const float* hvp = d_hidver + lv*256;
            #pragma unroll
            for (int qq = 0; qq < 8; ++qq) {
                int k = lane + 32*qq;
                hgdyn += __ldcg(&hvp[k]) * __ldg(&Wg[(256 + k)*256 + h]);
            }
            #pragma unroll
            for (int o = 16; o; o >>= 1)
                hgdyn += __shfl_xor_sync(0xffffffffu, hgdyn, o);
        }
        float HWi_e = lv_old ? hv_sel : sm[C::O_HW0G + t*W + wid];
        float fS_e = 0.f;
        if (lane == 0 && lv != t - 1) fS_e = sig_t(fsv + HWi_e);

        // ===== per-warp wait for hid[t-1] packet =====
        if (t > 0) {
            unsigned ok;
            do {
                unsigned f = (lane < NCTA) ? ld_acq_sh(flagbase + 4u*lane) : 0u;
                ok = __all_sync(0xffffffffu,
                                (lane < NCTA) ? (f >= (unsigned)t) : 1u);
            } while (!ok);
        }

        // ===== post-wait: dot + slot-(t-1) correction =====
        float hwnew = 0.f, c1 = 0.f, c2 = 0.f;
        if (t > 0) {
            const float4* hv4 = (const float4*)(sm + C::O_HIDB + pb*HH);
            const float4* wn4 = (const float4*)(sm + C::O_WN + wid*256);
            float4 x0 = hv4[lane*2],   a0 = wn4[lane*2];
            float4 x1 = hv4[lane*2+1], a1 = wn4[lane*2+1];
            hwnew = x0.x*a0.x + x0.y*a0.y + x0.z*a0.z + x0.w*a0.w
                  + x1.x*a1.x + x1.y*a1.y + x1.z*a1.z + x1.w*a1.w;
            #pragma unroll
            for (int o = 16; o; o >>= 1)
                hwnew += __shfl_xor_sync(0xffffffffu, hwnew, o);
            const int slot = t - 1, owner = slot & 31, q = slot >> 5;
            if (lane == owner) {
                float hbp;
                if (q == 0)      { hbp = hb0; hv0 = hwnew; }
                else if (q == 1) { hbp = hb1; hv1 = hwnew; }
                else if (q == 2) { hbp = hb2; hv2 = hwnew; }
                else             { hbp = hb3; hv3 = hwnew; }
                float w = pw[slot];
                c1 = w * (hwnew - hbp);
                c2 = w * (sig_t(fsv + hwnew) - sig_t(fsv + hbp));
            }
            c1 = __shfl_sync(0xffffffffu, c1, owner);
            c2 = __shfl_sync(0xffffffffu, c2, owner);
        }

        // rare: revisit of immediately preceding step
        if (lv == t - 1 && t > 0) {
            const float* hvp = sm + C::O_HIDB + pb*HH;
            float g = 0.f;
            #pragma unroll
            for (int qq = 0; qq < 8; ++qq) {
                int k = lane + 32*qq;
                g += hvp[k] * __ldg(&Wg[(256 + k)*256 + h]);
            }
            #pragma unroll
            for (int o = 16; o; o >>= 1)
                g += __shfl_xor_sync(0xffffffffu, g, o);
            hgdyn = g;
            hv_sel = hwnew;
        }

        // ===== gates (lane 0), MUFU via tanh.approx =====
        float hid_l0 = 0.f, HWi_l0 = 0.f;
        if (lane == 0) {
            const int eb = t*W + wid;
            float HWi, HGi, cprev, fS;
            if (lv >= 0) { HWi = hv_sel; HGi = hgdyn;
                           cprev = sm[C::O_CELL + lv*W + wid]; }
            else         { HWi = HWi_e; HGi = sm[C::O_HG0G + eb];
                           cprev = sm[C::O_C0 + eb]; }
            fS = (lv == t - 1) ? sig_t(fsv + HWi) : fS_e;
            float invn = sm[C::O_INV + t];
            float pre  = sm[C::O_GIPN + eb] + HGi + (s1p + c1) * invn;
            float S2n  = sm[C::O_S2N + eb] + (s2p + c2) * invn;
            float iS   = sig_t(pre);
            float hC   = tanh_a(pre);
            float cC   = fmaf(S2n, cprev, fmaf(fS, cprev, iS*hC));
            sm[C::O_CELL + eb] = cC;
            hid_l0 = tanh_a(iS * cC);
            __stcg(&d_hidver[t*256 + h], hid_l0);
            HWi_l0 = HWi;
        }
        float hidnew  = __shfl_sync(0xffffffffu, hid_l0, 0);
        float HWi_all = __shfl_sync(0xffffffffu, HWi_l0, 0);
        if (lane == (t & 31)) {
            int q = t >> 5;
            if (q == 0) hb0 = HWi_all; else if (q == 1) hb1 = HWi_all;
            else if (q == 2) hb2 = HWi_all; else hb3 = HWi_all;
        }

        // ===== push to all NCTA CTAs; warp0 releases flags after bar =====
        if (lane < NCTA) {
            uint32_t loc = smbase + (uint32_t)(C::O_HIDB + (t & 1)*HH + h) * 4u;
            st_rlx_rem(mapa_rank(loc, lane), hidnew);
        }
        if (wid == 0) {
            asm volatile("bar.sync 1, %0;" :: "r"(C::NT) : "memory");
            if (lane < NCTA)
                st_rel_rem(mapa_rank(flagbase + 4u*rank, lane), (unsigned)(t + 1));
        } else {
            asm volatile("bar.arrive 1, %0;" :: "r"(C::NT) : "memory");
        }
    }

    asm volatile("barrier.cluster.arrive.aligned;" ::: "memory");
    asm volatile("barrier.cluster.wait.aligned;" ::: "memory");
}

__global__ void __launch_bounds__(1024, 1) __cluster_dims__(8, 1, 1)
k_main8(const float* __restrict__ Wn, const float* __restrict__ Wg,
        const int* __restrict__ seq, const float* __restrict__ c0)
{ k_main_body<8>(Wn, Wg, seq, c0); }

__global__ void __launch_bounds__(512, 1)
k_main16(const float* __restrict__ Wn, const float* __restrict__ Wg,
         const int* __restrict__ seq, const float* __restrict__ c0)
{ k_main_body<16>(Wn, Wg, seq, c0); }

__global__ void __launch_bounds__(256) k_epi(const float* __restrict__ h0,
                                             float* __restrict__ out)
{
    for (int e = blockIdx.x*blockDim.x + threadIdx.x; e < NN*HH;
         e += gridDim.x*blockDim.x) {
        int node = e >> 8;
        int ls = __ldg(&d_lastStep[node]);
        float hval = (ls >= 0) ? d_hidver[ls*256 + (e & 255)] : __ldg(&h0[e]);
        out[e] = hval + __ldg(&h0[e]);
    }
}

extern "C" void kernel_launch(void* const* d_in, const int* in_sizes, int n_in,
                              void* d_out, int out_size) {
    const float* inputs  = (const float*)d_in[0];
    const float* nei     = (const float*)d_in[1];
    const float* numNei  = (const float*)d_in[2];
    const int*   seq     = (const int*)  d_in[3];
    const float* h0      = (const float*)d_in[4];
    const float* c0      = (const float*)d_in[5];
    const float* Wg      = (const float*)d_in[6];
    const float* bg      = (const float*)d_in[7];
    const float* Ws      = (const float*)d_in[8];
    const float* bs      = (const float*)d_in[9];
    const float* Wn      = (const float*)d_in[10];
    float* out = (float*)d_out;

    static int ncta_sel = 0;   // deterministic config choice, resolved once
    if (ncta_sel == 0) {
        cudaFuncSetAttribute(k_main8, cudaFuncAttributeMaxDynamicSharedMemorySize,
                             Cfg<8>::SMB);
        int ok16 = 0;
        if (cudaFuncSetAttribute(k_main16,
                cudaFuncAttributeNonPortableClusterSizeAllowed, 1) == cudaSuccess &&
            cudaFuncSetAttribute(k_main16,
                cudaFuncAttributeMaxDynamicSharedMemorySize, Cfg<16>::SMB) == cudaSuccess) {
            cudaLaunchConfig_t cfg = {};
            cfg.gridDim = dim3(16, 1, 1);
            cfg.blockDim = dim3(512, 1, 1);
            cfg.dynamicSmemBytes = Cfg<16>::SMB;
            cudaLaunchAttribute a[1];
            a[0].id = cudaLaunchAttributeClusterDimension;
            a[0].val.clusterDim = {16, 1, 1};
            cfg.attrs = a; cfg.numAttrs = 1;
            int num = 0;
            if (cudaOccupancyMaxActiveClusters(&num, k_main16, &cfg) == cudaSuccess
                && num >= 1)
                ok16 = 1;
        }
        cudaGetLastError();    // clear any probe error
        ncta_sel = ok16 ? 16 : 8;
    }

    k_init<<<16, 256>>>();
    k_pre1<<<SS, 256>>>(inputs, nei, numNei, seq, h0, Wg, bg, Ws, bs, Wn);
    k_pre2<<<dim3(SS/T_PER, NN/512), 256>>>(nei, seq);
    if (ncta_sel == 16) {
        cudaLaunchConfig_t cfg = {};
        cfg.gridDim = dim3(16, 1, 1);
        cfg.blockDim = dim3(512, 1, 1);
        cfg.dynamicSmemBytes = Cfg<16>::SMB;
        cudaLaunchAttribute a[1];
        a[0].id = cudaLaunchAttributeClusterDimension;
        a[0].val.clusterDim = {16, 1, 1};
        cfg.attrs = a; cfg.numAttrs = 1;
        cudaLaunchKernelEx(&cfg, k_main16, Wn, Wg, seq, c0);
    } else {
        k_main8<<<8, 1024, Cfg<8>::SMB>>>(Wn, Wg, seq, c0);
    }
    k_epi<<<148, 256>>>(h0, out);
}